// round 13
// baseline (speedup 1.0000x reference)
#include <cuda_runtime.h>
#include <cuda_fp16.h>
#include <cstdint>

// Fused 9-layer MLP via mma.sync fp16 (HMMA), single-pass fp16, fp32 accum.
// N=262144, IN=39(pad64), H=256, OUT=4.
// R13 = R10 (64 rows/CTA, 256 thr, 2 CTAs/SM, warp tile 64x32) with the
// inner loop fragment-staged: per ks stage ALL b (2 ldsm4t) and a (4 ldsm4)
// fragments, then issue 16 independent mmas back-to-back (no per-mf
// ldsm->mma latency chain).

#define THREADS 256
#define M_TILE  64
#define NROWS   262144

// 30 chunks of [64 k][256 n] fp16 each (row-major, k-major rows)
__device__ __align__(256) __half g_w[30 * 16384];

// ---- smem byte layout ----
#define WBUF_SZ  33792              // per buf: 64*528
#define SM_W     0                  // 2 bufs = 67584
#define SM_A     67584              // [64 rows][264 cols] fp16 = 33792
#define SM_X     101376             // [64 rows][72 cols] fp16 = 9216
#define SM_BIAS  110592             // 256 fp32
#define SM_W9    111616             // 1024 fp32
#define SM_TOTAL 115712

#define ASTR 528     // A row stride bytes (264 fp16)
#define XSTR 144     // x row stride bytes (72 fp16)
#define WSTR 528     // W smem row stride bytes (264 fp16, data in first 512B)

// ---------- PTX helpers (all baseline, no 'a' features) ----------
__device__ __forceinline__ uint32_t smem_u32(const void* p) {
    uint32_t a;
    asm("{ .reg .u64 t; cvta.to.shared.u64 t, %1; cvt.u32.u64 %0, t; }" : "=r"(a) : "l"(p));
    return a;
}
__device__ __forceinline__ void cpa16(uint8_t* s, const uint8_t* g) {
    uint32_t ss = smem_u32(s);
    asm volatile("cp.async.cg.shared.global [%0], [%1], 16;" :: "r"(ss), "l"(g));
}
__device__ __forceinline__ void cp_commit() { asm volatile("cp.async.commit_group;"); }
__device__ __forceinline__ void cp_wait0()  { asm volatile("cp.async.wait_group 0;"); }
__device__ __forceinline__ void cp_wait1()  { asm volatile("cp.async.wait_group 1;"); }

__device__ __forceinline__ void ldsm4(uint32_t* r, uint32_t addr) {
    asm volatile("ldmatrix.sync.aligned.m8n8.x4.shared.b16 {%0,%1,%2,%3}, [%4];"
                 : "=r"(r[0]), "=r"(r[1]), "=r"(r[2]), "=r"(r[3]) : "r"(addr));
}
__device__ __forceinline__ void ldsm4t(uint32_t* r, uint32_t addr) {
    asm volatile("ldmatrix.sync.aligned.m8n8.x4.trans.shared.b16 {%0,%1,%2,%3}, [%4];"
                 : "=r"(r[0]), "=r"(r[1]), "=r"(r[2]), "=r"(r[3]) : "r"(addr));
}
__device__ __forceinline__ void mma_f16(float* c, const uint32_t* a, uint32_t b0, uint32_t b1) {
    asm volatile(
        "mma.sync.aligned.m16n8k16.row.col.f32.f16.f16.f32 "
        "{%0,%1,%2,%3}, {%4,%5,%6,%7}, {%8,%9}, {%0,%1,%2,%3};"
        : "+f"(c[0]), "+f"(c[1]), "+f"(c[2]), "+f"(c[3])
        : "r"(a[0]), "r"(a[1]), "r"(a[2]), "r"(a[3]), "r"(b0), "r"(b1));
}

__device__ __forceinline__ uint32_t pack_h2(float v0, float v1) {
    __half h0 = __float2half_rn(v0);
    __half h1 = __float2half_rn(v1);
    return ((uint32_t)__half_as_ushort(h1) << 16) | __half_as_ushort(h0);
}

// ---------- prep: fp32 weights -> fp16 [k][n] chunks ----------
__global__ void __launch_bounds__(256) prep_kernel(
    const float* __restrict__ w1, const float* __restrict__ w2,
    const float* __restrict__ w3, const float* __restrict__ w4,
    const float* __restrict__ w5, const float* __restrict__ w6,
    const float* __restrict__ w7, const float* __restrict__ w8)
{
    int gid = blockIdx.x * 256 + threadIdx.x;   // 0 .. 491519
    int chunk = gid >> 14;
    int e = gid & 16383;
    int kl = e >> 8;       // k within chunk (0..63)
    int r  = e & 255;      // n (0..255)
    const float* src; int k0, Ksrc;
    if (chunk == 0)      { src = w1; k0 = 0;                 Ksrc = 39;  }
    else if (chunk < 5)  { src = w2; k0 = (chunk - 1) * 64;  Ksrc = 256; }
    else if (chunk < 9)  { src = w3; k0 = (chunk - 5) * 64;  Ksrc = 256; }
    else if (chunk < 13) { src = w4; k0 = (chunk - 9) * 64;  Ksrc = 256; }
    else if (chunk < 18) { src = w5; k0 = (chunk - 13) * 64; Ksrc = 295; }
    else if (chunk < 22) { src = w6; k0 = (chunk - 18) * 64; Ksrc = 256; }
    else if (chunk < 26) { src = w7; k0 = (chunk - 22) * 64; Ksrc = 256; }
    else                 { src = w8; k0 = (chunk - 26) * 64; Ksrc = 256; }
    int k = k0 + kl;
    float v = (k < Ksrc) ? src[k * 256 + r] : 0.0f;
    g_w[gid] = __float2half_rn(v);
}

// ---------- main fused kernel ----------
__device__ __forceinline__ void stage_chunk(uint8_t* sm, int buf, int chunk, int tid) {
    const uint8_t* s = (const uint8_t*)(g_w + chunk * 16384);
    uint8_t* d = sm + SM_W + buf * WBUF_SZ;
#pragma unroll
    for (int i = tid; i < 2048; i += THREADS) {
        int row = i >> 5, j = i & 31;
        cpa16(d + row * WSTR + j * 16, s + i * 16);
    }
    cp_commit();
}

// warp tile 64x32: C[4 mf][4 nf][4]; per ks: stage all b + a, then 16 mmas.
__device__ __forceinline__ void compute_chunk(
    float C[4][4][4],
    uint32_t a_base, int astr,
    uint32_t w_base,
    int lane, int col0w)
{
    const int quad = lane >> 3;
    const int qr   = lane & 7;
    const int arow_off = ((quad & 1) << 3) + qr;   // row within 16-tile
    const int acol_off = (quad >> 1) << 3;         // k offset within 16
    const int brow_off = ((quad & 1) << 3) + qr;   // k within 16-tile
    const int bcol_off = (quad >> 1) << 3;         // n offset within 16

#pragma unroll
    for (int ks = 0; ks < 4; ks++) {
        const int k0 = ks * 16;
        uint32_t b[2][4];
#pragma unroll
        for (int np = 0; np < 2; np++) {
            int krow = k0 + brow_off;
            int ncol = col0w + np * 16 + bcol_off;
            ldsm4t(b[np], w_base + (uint32_t)(krow * WSTR + ncol * 2));
        }
        uint32_t a[4][4];
#pragma unroll
        for (int mf = 0; mf < 4; mf++) {
            int row = mf * 16 + arow_off;
            int kk  = k0 + acol_off;
            ldsm4(a[mf], a_base + (uint32_t)(row * astr + kk * 2));
        }
        // 16 independent mmas (all distinct C fragments)
#pragma unroll
        for (int mf = 0; mf < 4; mf++) {
#pragma unroll
            for (int np = 0; np < 2; np++) {
#pragma unroll
                for (int ns = 0; ns < 2; ns++) {
                    mma_f16(C[mf][np * 2 + ns], a[mf], b[np][2 * ns], b[np][2 * ns + 1]);
                }
            }
        }
    }
}

__global__ void __launch_bounds__(THREADS, 2) mlp_mma_kernel(
    const float* __restrict__ x,
    const float* __restrict__ b1, const float* __restrict__ b2,
    const float* __restrict__ b3, const float* __restrict__ b4,
    const float* __restrict__ b5, const float* __restrict__ b6,
    const float* __restrict__ b7, const float* __restrict__ b8,
    const float* __restrict__ w9, const float* __restrict__ b9,
    float* __restrict__ out)
{
    extern __shared__ uint8_t sm[];
    const int tid  = threadIdx.x;
    const int wid  = tid >> 5;
    const int lane = tid & 31;
    const int col0w = wid * 32;          // warp n-offset (0..224); rows 0..63 all warps
    const int row0 = blockIdx.x * M_TILE;

    float* bsm = (float*)(sm + SM_BIAS);
    float* w9s = (float*)(sm + SM_W9);
    const uint32_t a_base = smem_u32(sm + SM_A);
    const uint32_t x_base = smem_u32(sm + SM_X);

    static const int CB[8]  = {0, 1, 5, 9, 13, 18, 22, 26};
    static const int NCK[8] = {1, 4, 4, 4, 5,  4,  4,  4};

    // prologue: stage chunk 0 into buf 0
    stage_chunk(sm, 0, 0, tid);

    // stage x tile (fp16) and w9
    {
        __half* xh = (__half*)(sm + SM_X);
        for (int i = tid; i < M_TILE * 64; i += THREADS) {
            int r = i >> 6, k = i & 63;
            float v = (k < 39) ? x[(size_t)(row0 + r) * 39 + k] : 0.0f;
            xh[r * 72 + k] = __float2half_rn(v);
        }
        for (int i = tid; i < 1024; i += THREADS) w9s[i] = w9[i];
    }

    const float* Bl[8] = {b1, b2, b3, b4, b5, b6, b7, b8};
    int bi = 0;

    for (int l = 0; l < 8; l++) {
        bsm[tid] = Bl[l][tid];

        float C[4][4][4];
#pragma unroll
        for (int i = 0; i < 4; i++)
#pragma unroll
            for (int j = 0; j < 4; j++)
#pragma unroll
                for (int q = 0; q < 4; q++) C[i][j][q] = 0.0f;

        const int nck = NCK[l];
        for (int c = 0; c < nck; c++) {
            int nxt = (c + 1 < nck) ? (CB[l] + c + 1) : ((l < 7) ? CB[l + 1] : -1);
            if (nxt >= 0) { stage_chunk(sm, bi ^ 1, nxt, tid); cp_wait1(); }
            else          { cp_wait0(); }
            __syncthreads();

            const uint32_t wh = smem_u32(sm + SM_W + bi * WBUF_SZ);
            const bool usex = (l == 0) || (l == 4 && c == 4);
            // chunk c of a multi-chunk layer reads A k-range [64c, 64c+63]
            const uint32_t akoff = usex ? 0u : (uint32_t)(c * 128);  // 64 cols * 2B
            compute_chunk(C,
                          (usex ? x_base : a_base) + akoff,
                          usex ? XSTR : ASTR,
                          wh, lane, col0w);
            __syncthreads();
            bi ^= 1;
        }

        if (l < 7) {
            // epilogue: bias + relu, write A in place (fp16)
#pragma unroll
            for (int mf = 0; mf < 4; mf++) {
#pragma unroll
                for (int nf = 0; nf < 4; nf++) {
                    int col = col0w + nf * 8 + 2 * (lane & 3);
                    int rA  = mf * 16 + (lane >> 2);
                    float* cc = C[mf][nf];
                    float v0 = fmaxf(cc[0] + bsm[col],     0.0f);
                    float v1 = fmaxf(cc[1] + bsm[col + 1], 0.0f);
                    float v2 = fmaxf(cc[2] + bsm[col],     0.0f);
                    float v3 = fmaxf(cc[3] + bsm[col + 1], 0.0f);
                    uint32_t off  = (uint32_t)(rA * ASTR + col * 2);
                    uint32_t off2 = off + 8u * ASTR;
                    *(uint32_t*)(sm + SM_A + off)  = pack_h2(v0, v1);
                    *(uint32_t*)(sm + SM_A + off2) = pack_h2(v2, v3);
                }
            }
            __syncthreads();
        } else {
            // final epilogue: relu(h)+bias, then x w9 (256->4), reduce via smem atomics
            float* scr = (float*)sm;            // 256 floats (W bufs dead now)
            scr[tid] = 0.0f;
            __syncthreads();
            float p[8][4];
#pragma unroll
            for (int i = 0; i < 8; i++)
#pragma unroll
                for (int j = 0; j < 4; j++) p[i][j] = 0.0f;
#pragma unroll
            for (int mf = 0; mf < 4; mf++) {
#pragma unroll
                for (int nf = 0; nf < 4; nf++) {
                    int col = col0w + nf * 8 + 2 * (lane & 3);
                    float* cc = C[mf][nf];
                    float v0 = fmaxf(cc[0] + bsm[col],     0.0f);
                    float v1 = fmaxf(cc[1] + bsm[col + 1], 0.0f);
                    float v2 = fmaxf(cc[2] + bsm[col],     0.0f);
                    float v3 = fmaxf(cc[3] + bsm[col + 1], 0.0f);
                    const float* wc0 = w9s + col * 4;
                    const float* wc1 = w9s + (col + 1) * 4;
#pragma unroll
                    for (int j = 0; j < 4; j++) {
                        p[2 * mf][j]     += v0 * wc0[j] + v1 * wc1[j];
                        p[2 * mf + 1][j] += v2 * wc0[j] + v3 * wc1[j];
                    }
                }
            }
#pragma unroll
            for (int rr = 0; rr < 8; rr++) {
                int row = (rr >> 1) * 16 + (rr & 1) * 8 + (lane >> 2);
#pragma unroll
                for (int j = 0; j < 4; j++)
                    atomicAdd(scr + row * 4 + j, p[rr][j]);
            }
            __syncthreads();
            out[(size_t)(row0 + (tid >> 2)) * 4 + (tid & 3)] = scr[tid] + b9[tid & 3];
        }
    }
}

extern "C" void kernel_launch(void* const* d_in, const int* in_sizes, int n_in,
                              void* d_out, int out_size)
{
    const float* x  = (const float*)d_in[0];
    const float* w1 = (const float*)d_in[1],  *b1 = (const float*)d_in[2];
    const float* w2 = (const float*)d_in[3],  *b2 = (const float*)d_in[4];
    const float* w3 = (const float*)d_in[5],  *b3 = (const float*)d_in[6];
    const float* w4 = (const float*)d_in[7],  *b4 = (const float*)d_in[8];
    const float* w5 = (const float*)d_in[9],  *b5 = (const float*)d_in[10];
    const float* w6 = (const float*)d_in[11], *b6 = (const float*)d_in[12];
    const float* w7 = (const float*)d_in[13], *b7 = (const float*)d_in[14];
    const float* w8 = (const float*)d_in[15], *b8 = (const float*)d_in[16];
    const float* w9 = (const float*)d_in[17], *b9 = (const float*)d_in[18];
    float* out = (float*)d_out;

    prep_kernel<<<1920, 256>>>(w1, w2, w3, w4, w5, w6, w7, w8);

    cudaFuncSetAttribute(mlp_mma_kernel,
                         cudaFuncAttributeMaxDynamicSharedMemorySize, SM_TOTAL);
    mlp_mma_kernel<<<NROWS / M_TILE, THREADS, SM_TOTAL>>>(
        x, b1, b2, b3, b4, b5, b6, b7, b8, w9, b9, out);
}

// round 14
// speedup vs baseline: 1.0444x; 1.0444x over previous
#include <cuda_runtime.h>
#include <cuda_fp16.h>
#include <cstdint>

// Fused 9-layer MLP via mma.sync fp16 (HMMA), single-pass fp16, fp32 accum.
// N=262144, IN=39(pad64), H=256, OUT=4.
// R14: CTA = 64 rows, 128 threads (4 warps), warp tile 64x64, 2 CTAs/SM.
// 8 ldsm feed 32 mmas per ks (2x arithmetic intensity vs R10); 256 regs/thread
// available so C[128]+frags fit without spills. w9 read from global (L2).

#define THREADS 128
#define M_TILE  64
#define NROWS   262144

// 30 chunks of [64 k][256 n] fp16 each (row-major, k-major rows)
__device__ __align__(256) __half g_w[30 * 16384];

// ---- smem byte layout ----
#define WBUF_SZ  33792              // per buf: 64*528
#define SM_W     0                  // 2 bufs = 67584
#define SM_A     67584              // [64 rows][264 cols] fp16 = 33792
#define SM_X     101376             // [64 rows][72 cols] fp16 = 9216
#define SM_BIAS  110592             // 256 fp32 = 1024
#define SM_TOTAL 111616             // x2 CTAs = 223232 <= 227KB

#define ASTR 528     // A row stride bytes (264 fp16)
#define XSTR 144     // x row stride bytes (72 fp16)
#define WSTR 528     // W smem row stride bytes (264 fp16, data in first 512B)

// ---------- PTX helpers (all baseline, no 'a' features) ----------
__device__ __forceinline__ uint32_t smem_u32(const void* p) {
    uint32_t a;
    asm("{ .reg .u64 t; cvta.to.shared.u64 t, %1; cvt.u32.u64 %0, t; }" : "=r"(a) : "l"(p));
    return a;
}
__device__ __forceinline__ void cpa16(uint8_t* s, const uint8_t* g) {
    uint32_t ss = smem_u32(s);
    asm volatile("cp.async.cg.shared.global [%0], [%1], 16;" :: "r"(ss), "l"(g));
}
__device__ __forceinline__ void cp_commit() { asm volatile("cp.async.commit_group;"); }
__device__ __forceinline__ void cp_wait0()  { asm volatile("cp.async.wait_group 0;"); }
__device__ __forceinline__ void cp_wait1()  { asm volatile("cp.async.wait_group 1;"); }

__device__ __forceinline__ void ldsm4(uint32_t* r, uint32_t addr) {
    asm volatile("ldmatrix.sync.aligned.m8n8.x4.shared.b16 {%0,%1,%2,%3}, [%4];"
                 : "=r"(r[0]), "=r"(r[1]), "=r"(r[2]), "=r"(r[3]) : "r"(addr));
}
__device__ __forceinline__ void ldsm4t(uint32_t* r, uint32_t addr) {
    asm volatile("ldmatrix.sync.aligned.m8n8.x4.trans.shared.b16 {%0,%1,%2,%3}, [%4];"
                 : "=r"(r[0]), "=r"(r[1]), "=r"(r[2]), "=r"(r[3]) : "r"(addr));
}
__device__ __forceinline__ void mma_f16(float* c, const uint32_t* a, uint32_t b0, uint32_t b1) {
    asm volatile(
        "mma.sync.aligned.m16n8k16.row.col.f32.f16.f16.f32 "
        "{%0,%1,%2,%3}, {%4,%5,%6,%7}, {%8,%9}, {%0,%1,%2,%3};"
        : "+f"(c[0]), "+f"(c[1]), "+f"(c[2]), "+f"(c[3])
        : "r"(a[0]), "r"(a[1]), "r"(a[2]), "r"(a[3]), "r"(b0), "r"(b1));
}

__device__ __forceinline__ uint32_t pack_h2(float v0, float v1) {
    __half h0 = __float2half_rn(v0);
    __half h1 = __float2half_rn(v1);
    return ((uint32_t)__half_as_ushort(h1) << 16) | __half_as_ushort(h0);
}

// ---------- prep: fp32 weights -> fp16 [k][n] chunks ----------
__global__ void __launch_bounds__(256) prep_kernel(
    const float* __restrict__ w1, const float* __restrict__ w2,
    const float* __restrict__ w3, const float* __restrict__ w4,
    const float* __restrict__ w5, const float* __restrict__ w6,
    const float* __restrict__ w7, const float* __restrict__ w8)
{
    int gid = blockIdx.x * 256 + threadIdx.x;   // 0 .. 491519
    int chunk = gid >> 14;
    int e = gid & 16383;
    int kl = e >> 8;       // k within chunk (0..63)
    int r  = e & 255;      // n (0..255)
    const float* src; int k0, Ksrc;
    if (chunk == 0)      { src = w1; k0 = 0;                 Ksrc = 39;  }
    else if (chunk < 5)  { src = w2; k0 = (chunk - 1) * 64;  Ksrc = 256; }
    else if (chunk < 9)  { src = w3; k0 = (chunk - 5) * 64;  Ksrc = 256; }
    else if (chunk < 13) { src = w4; k0 = (chunk - 9) * 64;  Ksrc = 256; }
    else if (chunk < 18) { src = w5; k0 = (chunk - 13) * 64; Ksrc = 295; }
    else if (chunk < 22) { src = w6; k0 = (chunk - 18) * 64; Ksrc = 256; }
    else if (chunk < 26) { src = w7; k0 = (chunk - 22) * 64; Ksrc = 256; }
    else                 { src = w8; k0 = (chunk - 26) * 64; Ksrc = 256; }
    int k = k0 + kl;
    float v = (k < Ksrc) ? src[k * 256 + r] : 0.0f;
    g_w[gid] = __float2half_rn(v);
}

// ---------- main fused kernel ----------
__device__ __forceinline__ void stage_chunk(uint8_t* sm, int buf, int chunk, int tid) {
    const uint8_t* s = (const uint8_t*)(g_w + chunk * 16384);
    uint8_t* d = sm + SM_W + buf * WBUF_SZ;
#pragma unroll
    for (int i = tid; i < 2048; i += THREADS) {
        int row = i >> 5, j = i & 31;
        cpa16(d + row * WSTR + j * 16, s + i * 16);
    }
    cp_commit();
}

// warp tile 64x64: C[4 mf][8 nf][4]; per ks: 4 ldsm4t(B) + 4 ldsm4(A), 32 mmas.
__device__ __forceinline__ void compute_chunk(
    float C[4][8][4],
    uint32_t a_base, int astr,
    uint32_t w_base,
    int lane, int col0w)
{
    const int quad = lane >> 3;
    const int qr   = lane & 7;
    const int arow_off = ((quad & 1) << 3) + qr;   // row within 16-tile
    const int acol_off = (quad >> 1) << 3;         // k offset within 16
    const int brow_off = ((quad & 1) << 3) + qr;   // k within 16-tile
    const int bcol_off = (quad >> 1) << 3;         // n offset within 16

#pragma unroll
    for (int ks = 0; ks < 4; ks++) {
        const int k0 = ks * 16;
        uint32_t b[4][4];
#pragma unroll
        for (int np = 0; np < 4; np++) {
            int krow = k0 + brow_off;
            int ncol = col0w + np * 16 + bcol_off;
            ldsm4t(b[np], w_base + (uint32_t)(krow * WSTR + ncol * 2));
        }
#pragma unroll
        for (int mf = 0; mf < 4; mf++) {
            uint32_t a[4];
            int row = mf * 16 + arow_off;
            int kk  = k0 + acol_off;
            ldsm4(a, a_base + (uint32_t)(row * astr + kk * 2));
#pragma unroll
            for (int np = 0; np < 4; np++) {
#pragma unroll
                for (int ns = 0; ns < 2; ns++) {
                    mma_f16(C[mf][np * 2 + ns], a, b[np][2 * ns], b[np][2 * ns + 1]);
                }
            }
        }
    }
}

__global__ void __launch_bounds__(THREADS, 2) mlp_mma_kernel(
    const float* __restrict__ x,
    const float* __restrict__ b1, const float* __restrict__ b2,
    const float* __restrict__ b3, const float* __restrict__ b4,
    const float* __restrict__ b5, const float* __restrict__ b6,
    const float* __restrict__ b7, const float* __restrict__ b8,
    const float* __restrict__ w9, const float* __restrict__ b9,
    float* __restrict__ out)
{
    extern __shared__ uint8_t sm[];
    const int tid  = threadIdx.x;
    const int wid  = tid >> 5;
    const int lane = tid & 31;
    const int col0w = wid * 64;          // warp n-offset (0/64/128/192)
    const int row0 = blockIdx.x * M_TILE;

    float* bsm = (float*)(sm + SM_BIAS);
    const uint32_t a_base = smem_u32(sm + SM_A);
    const uint32_t x_base = smem_u32(sm + SM_X);

    static const int CB[8]  = {0, 1, 5, 9, 13, 18, 22, 26};
    static const int NCK[8] = {1, 4, 4, 4, 5,  4,  4,  4};

    // prologue: stage chunk 0 into buf 0
    stage_chunk(sm, 0, 0, tid);

    // stage x tile (fp16)
    {
        __half* xh = (__half*)(sm + SM_X);
        for (int i = tid; i < M_TILE * 64; i += THREADS) {
            int r = i >> 6, k = i & 63;
            float v = (k < 39) ? x[(size_t)(row0 + r) * 39 + k] : 0.0f;
            xh[r * 72 + k] = __float2half_rn(v);
        }
    }

    const float* Bl[8] = {b1, b2, b3, b4, b5, b6, b7, b8};
    int bi = 0;

    for (int l = 0; l < 8; l++) {
        for (int i = tid; i < 256; i += THREADS) bsm[i] = Bl[l][i];

        float C[4][8][4];
#pragma unroll
        for (int i = 0; i < 4; i++)
#pragma unroll
            for (int j = 0; j < 8; j++)
#pragma unroll
                for (int q = 0; q < 4; q++) C[i][j][q] = 0.0f;

        const int nck = NCK[l];
        for (int c = 0; c < nck; c++) {
            int nxt = (c + 1 < nck) ? (CB[l] + c + 1) : ((l < 7) ? CB[l + 1] : -1);
            if (nxt >= 0) { stage_chunk(sm, bi ^ 1, nxt, tid); cp_wait1(); }
            else          { cp_wait0(); }
            __syncthreads();

            const uint32_t wh = smem_u32(sm + SM_W + bi * WBUF_SZ);
            const bool usex = (l == 0) || (l == 4 && c == 4);
            // chunk c of a multi-chunk layer reads A k-range [64c, 64c+63]
            const uint32_t akoff = usex ? 0u : (uint32_t)(c * 128);  // 64 cols * 2B
            compute_chunk(C,
                          (usex ? x_base : a_base) + akoff,
                          usex ? XSTR : ASTR,
                          wh, lane, col0w);
            __syncthreads();
            bi ^= 1;
        }

        if (l < 7) {
            // epilogue: bias + relu, write A in place (fp16)
#pragma unroll
            for (int mf = 0; mf < 4; mf++) {
#pragma unroll
                for (int nf = 0; nf < 8; nf++) {
                    int col = col0w + nf * 8 + 2 * (lane & 3);
                    int rA  = mf * 16 + (lane >> 2);
                    float* cc = C[mf][nf];
                    float v0 = fmaxf(cc[0] + bsm[col],     0.0f);
                    float v1 = fmaxf(cc[1] + bsm[col + 1], 0.0f);
                    float v2 = fmaxf(cc[2] + bsm[col],     0.0f);
                    float v3 = fmaxf(cc[3] + bsm[col + 1], 0.0f);
                    uint32_t off  = (uint32_t)(rA * ASTR + col * 2);
                    uint32_t off2 = off + 8u * ASTR;
                    *(uint32_t*)(sm + SM_A + off)  = pack_h2(v0, v1);
                    *(uint32_t*)(sm + SM_A + off2) = pack_h2(v2, v3);
                }
            }
            __syncthreads();
        } else {
            // final epilogue: relu(h)+bias, then x w9 (256->4), reduce via smem atomics
            // w9 read directly from global (4KB, L2-resident)
            float* scr = (float*)sm;            // 256 floats (W bufs dead now)
            for (int i = tid; i < 256; i += THREADS) scr[i] = 0.0f;
            __syncthreads();
            float p[8][4];
#pragma unroll
            for (int i = 0; i < 8; i++)
#pragma unroll
                for (int j = 0; j < 4; j++) p[i][j] = 0.0f;
#pragma unroll
            for (int mf = 0; mf < 4; mf++) {
#pragma unroll
                for (int nf = 0; nf < 8; nf++) {
                    int col = col0w + nf * 8 + 2 * (lane & 3);
                    float* cc = C[mf][nf];
                    float v0 = fmaxf(cc[0] + bsm[col],     0.0f);
                    float v1 = fmaxf(cc[1] + bsm[col + 1], 0.0f);
                    float v2 = fmaxf(cc[2] + bsm[col],     0.0f);
                    float v3 = fmaxf(cc[3] + bsm[col + 1], 0.0f);
                    const float* wc0 = w9 + col * 4;
                    const float* wc1 = w9 + (col + 1) * 4;
#pragma unroll
                    for (int j = 0; j < 4; j++) {
                        p[2 * mf][j]     += v0 * wc0[j] + v1 * wc1[j];
                        p[2 * mf + 1][j] += v2 * wc0[j] + v3 * wc1[j];
                    }
                }
            }
#pragma unroll
            for (int rr = 0; rr < 8; rr++) {
                int row = (rr >> 1) * 16 + (rr & 1) * 8 + (lane >> 2);
#pragma unroll
                for (int j = 0; j < 4; j++)
                    atomicAdd(scr + row * 4 + j, p[rr][j]);
            }
            __syncthreads();
            for (int i = tid; i < 256; i += THREADS)
                out[(size_t)(row0 + (i >> 2)) * 4 + (i & 3)] = scr[i] + b9[i & 3];
        }
    }
}

extern "C" void kernel_launch(void* const* d_in, const int* in_sizes, int n_in,
                              void* d_out, int out_size)
{
    const float* x  = (const float*)d_in[0];
    const float* w1 = (const float*)d_in[1],  *b1 = (const float*)d_in[2];
    const float* w2 = (const float*)d_in[3],  *b2 = (const float*)d_in[4];
    const float* w3 = (const float*)d_in[5],  *b3 = (const float*)d_in[6];
    const float* w4 = (const float*)d_in[7],  *b4 = (const float*)d_in[8];
    const float* w5 = (const float*)d_in[9],  *b5 = (const float*)d_in[10];
    const float* w6 = (const float*)d_in[11], *b6 = (const float*)d_in[12];
    const float* w7 = (const float*)d_in[13], *b7 = (const float*)d_in[14];
    const float* w8 = (const float*)d_in[15], *b8 = (const float*)d_in[16];
    const float* w9 = (const float*)d_in[17], *b9 = (const float*)d_in[18];
    float* out = (float*)d_out;

    prep_kernel<<<1920, 256>>>(w1, w2, w3, w4, w5, w6, w7, w8);

    cudaFuncSetAttribute(mlp_mma_kernel,
                         cudaFuncAttributeMaxDynamicSharedMemorySize, SM_TOTAL);
    mlp_mma_kernel<<<NROWS / M_TILE, THREADS, SM_TOTAL>>>(
        x, b1, b2, b3, b4, b5, b6, b7, b8, w9, b9, out);
}